// round 17
// baseline (speedup 1.0000x reference)
#include <cuda_runtime.h>
#include <cstdint>

#define BS_  16
#define SEQQ 2048
#define DIM  1024
#define KDIM 1024
#define AH   64
#define HR   256
#define RANKD 16
#define KR   64
#define LQ   128
#define HID  2048

// ---- scratch (no allocations allowed; __device__ globals are the sanctioned path) ----
__device__ float g_Qp [BS_*SEQQ*DIM];
__device__ float g_Kp [BS_*KDIM*DIM];
__device__ float g_Vp [BS_*KDIM*DIM];
__device__ float g_kf [BS_*AH*HR*RANKD];
__device__ float g_vf [BS_*AH*HR*RANKD];
__device__ float g_ctx[BS_*SEQQ*DIM];
__device__ float g_h1 [BS_*SEQQ*HID];
__device__ float g_y  [BS_*SEQQ*DIM];

// ============================================================================
// helpers
// ============================================================================
__device__ __forceinline__ uint32_t f2tf(float x) {
    uint32_t r;
    asm("cvt.rna.tf32.f32 %0, %1;" : "=r"(r) : "f"(x));
    return r;
}

__device__ __forceinline__ void mma_tf32(float* d, const uint32_t* a, const uint32_t* b) {
    asm volatile(
        "mma.sync.aligned.m16n8k8.row.col.f32.tf32.tf32.f32 "
        "{%0,%1,%2,%3}, {%4,%5,%6,%7}, {%8,%9}, {%0,%1,%2,%3};"
        : "+f"(d[0]), "+f"(d[1]), "+f"(d[2]), "+f"(d[3])
        : "r"(a[0]), "r"(a[1]), "r"(a[2]), "r"(a[3]), "r"(b[0]), "r"(b[1]));
}

__device__ __forceinline__ uint32_t smem_u32(const void* p) {
    uint32_t r;
    asm("{ .reg .u64 t; cvta.to.shared.u64 t, %1; cvt.u32.u64 %0, t; }"
        : "=r"(r) : "l"(p));
    return r;
}

__device__ __forceinline__ void cp16(uint32_t dst, const float* src) {
    asm volatile("cp.async.cg.shared.global [%0], [%1], 16;" :: "r"(dst), "l"(src));
}

#define LDW   36                          // smem row stride in words (bank-bijective)
#define STGW  (128 * LDW)                 // words per matrix per stage
#define GEMM_SMEM (4 * STGW * 4)          // [A0|A1|B0|B1] = 73728 B

// ============================================================================
// TF32 mma.sync GEMM, 64x64 warp tiles:
//   C[m,n] = sum_k A[m,k]*B[n,k] + bias[n]
// A [M,K], B [N,K] row-major. M%128==0, N%128==0, K%32==0.
// CTA tile 128x128x32, 4 warps (2m x 2n), warp tile 64x64, m16n8k8 tf32.
// 2-stage cp.async; tf32 rounding (cvt.rna) at fragment read.
// ============================================================================
template<bool RELU>
__global__ __launch_bounds__(128)
void tgemm_bias(const float* __restrict__ A, const float* __restrict__ B,
                const float* __restrict__ bias, float* __restrict__ C,
                int M, int N, int K)
{
    extern __shared__ float sm[];   // [A s0 | A s1 | B s0 | B s1]

    const int tid  = threadIdx.x;
    const int lane = tid & 31;
    const int warp = tid >> 5;
    const int wm   = (warp & 1) * 64;
    const int wn   = (warp >> 1) * 64;
    const int bm   = blockIdx.y * 128;
    const int bn   = blockIdx.x * 128;

    const int qr = lane >> 2;   // 0..7
    const int qc = lane & 3;    // 0..3

    // global->smem mapping: 8 threads per row (16B each), 16 rows/pass, 8 passes
    const int lr = tid >> 3;            // 0..15
    const int ch = tid & 7;             // 16B chunk within the 128B row
    const float* Ag = A + (size_t)(bm + lr) * K + ch * 4;
    const float* Bg = B + (size_t)(bn + lr) * K + ch * 4;

    const uint32_t sm_u = smem_u32(sm);
    const uint32_t dA0  = sm_u + (uint32_t)((lr * LDW + ch * 4) * 4);
    const uint32_t dB0  = dA0 + 2 * STGW * 4;

    float acc[4][8][4];
#pragma unroll
    for (int i = 0; i < 4; i++)
#pragma unroll
        for (int j = 0; j < 8; j++)
#pragma unroll
            for (int t = 0; t < 4; t++) acc[i][j][t] = 0.f;

    const int nt = K >> 5;

    // ---- prologue: prefetch tile 0 into stage 0 ----
#pragma unroll
    for (int it = 0; it < 8; it++) {
        cp16(dA0 + (uint32_t)(it * 16 * LDW * 4), Ag + (size_t)(it * 16) * K);
        cp16(dB0 + (uint32_t)(it * 16 * LDW * 4), Bg + (size_t)(it * 16) * K);
    }
    asm volatile("cp.async.commit_group;" ::: "memory");

    for (int t = 0; t < nt; t++) {
        const int s = t & 1;
        if (t + 1 < nt) {
            const int k0 = (t + 1) << 5;
            const uint32_t off = (uint32_t)((s ^ 1) * STGW * 4);
#pragma unroll
            for (int it = 0; it < 8; it++) {
                cp16(dA0 + off + (uint32_t)(it * 16 * LDW * 4), Ag + (size_t)(it * 16) * K + k0);
                cp16(dB0 + off + (uint32_t)(it * 16 * LDW * 4), Bg + (size_t)(it * 16) * K + k0);
            }
            asm volatile("cp.async.commit_group;" ::: "memory");
            asm volatile("cp.async.wait_group 1;" ::: "memory");
        } else {
            asm volatile("cp.async.wait_group 0;" ::: "memory");
        }
        __syncthreads();

        const float* Asb = sm + s * STGW;
        const float* Bsb = sm + (2 + s) * STGW;

#pragma unroll
        for (int kk = 0; kk < 32; kk += 8) {
            uint32_t af[4][4];
#pragma unroll
            for (int i = 0; i < 4; i++) {
                const int r = wm + i * 16;
                af[i][0] = f2tf(Asb[(r + qr    ) * LDW + kk + qc    ]);
                af[i][1] = f2tf(Asb[(r + qr + 8) * LDW + kk + qc    ]);
                af[i][2] = f2tf(Asb[(r + qr    ) * LDW + kk + qc + 4]);
                af[i][3] = f2tf(Asb[(r + qr + 8) * LDW + kk + qc + 4]);
            }
            uint32_t bf[8][2];
#pragma unroll
            for (int j = 0; j < 8; j++) {
                const int c = wn + j * 8;
                bf[j][0] = f2tf(Bsb[(c + qr) * LDW + kk + qc    ]);
                bf[j][1] = f2tf(Bsb[(c + qr) * LDW + kk + qc + 4]);
            }
#pragma unroll
            for (int i = 0; i < 4; i++)
#pragma unroll
                for (int j = 0; j < 8; j++)
                    mma_tf32(acc[i][j], af[i], bf[j]);
        }
        __syncthreads();   // stage s free before iter t+1 prefetches into it
    }

    // ---- epilogue: bias (+ReLU), float2 stores ----
    float bv0[8], bv1[8];
#pragma unroll
    for (int j = 0; j < 8; j++) {
        const int col = bn + wn + j * 8 + qc * 2;
        bv0[j] = bias[col];
        bv1[j] = bias[col + 1];
    }
#pragma unroll
    for (int i = 0; i < 4; i++) {
        const int r0 = bm + wm + i * 16 + qr;
#pragma unroll
        for (int j = 0; j < 8; j++) {
            const int col = bn + wn + j * 8 + qc * 2;
            float v0 = acc[i][j][0] + bv0[j];
            float v1 = acc[i][j][1] + bv1[j];
            float v2 = acc[i][j][2] + bv0[j];
            float v3 = acc[i][j][3] + bv1[j];
            if (RELU) {
                v0 = fmaxf(v0, 0.f); v1 = fmaxf(v1, 0.f);
                v2 = fmaxf(v2, 0.f); v3 = fmaxf(v3, 0.f);
            }
            *(float2*)&C[(size_t)r0 * N + col]       = make_float2(v0, v1);
            *(float2*)&C[(size_t)(r0 + 8) * N + col] = make_float2(v2, v3);
        }
    }
}

// ============================================================================
// Low-rank factor projection (float4-vectorized input loads)
// ============================================================================
__global__ __launch_bounds__(256)
void factor_kernel(const float* __restrict__ Kp, const float* __restrict__ Vp,
                   const float* __restrict__ fac,
                   float* __restrict__ kf, float* __restrict__ vf)
{
    __shared__ float fs[KR][RANKD];
    const int a = blockIdx.x, b = blockIdx.y, h = threadIdx.x;

    for (int i = threadIdx.x; i < KR * RANKD; i += 256)
        ((float*)fs)[i] = fac[(size_t)a * KR * RANKD + i];
    __syncthreads();

    const size_t rowbase = ((size_t)b * KDIM + a * 16 + (h >> 4)) * DIM + (h & 15) * 64;
    const float4* kin = (const float4*)(Kp + rowbase);
    const float4* vin = (const float4*)(Vp + rowbase);

    float ak[RANKD], av[RANKD];
#pragma unroll
    for (int r = 0; r < RANKD; r++) { ak[r] = 0.f; av[r] = 0.f; }

#pragma unroll 4
    for (int q = 0; q < KR / 4; q++) {
        float4 k4 = kin[q];
        float4 v4 = vin[q];
        const float kv[4] = {k4.x, k4.y, k4.z, k4.w};
        const float vv[4] = {v4.x, v4.y, v4.z, v4.w};
#pragma unroll
        for (int s = 0; s < 4; s++) {
            const int kk = q * 4 + s;
#pragma unroll
            for (int r = 0; r < RANKD; r++) {
                ak[r] = fmaf(kv[s], fs[kk][r], ak[r]);
                av[r] = fmaf(vv[s], fs[kk][r], av[r]);
            }
        }
    }

    float4* ko = (float4*)(kf + (((size_t)b * AH + a) * HR + h) * RANKD);
    float4* vo = (float4*)(vf + (((size_t)b * AH + a) * HR + h) * RANKD);
#pragma unroll
    for (int r = 0; r < 4; r++) {
        ko[r] = make_float4(ak[4*r], ak[4*r+1], ak[4*r+2], ak[4*r+3]);
        vo[r] = make_float4(av[4*r], av[4*r+1], av[4*r+2], av[4*r+3]);
    }
}

// ============================================================================
// Fused attention per (b,a): scores + softmax(16) + ctx, written in (bs,seq,dim).
// ============================================================================
__global__ __launch_bounds__(128)
void attn_kernel(const float* __restrict__ Qp, const float* __restrict__ kf,
                 const float* __restrict__ vf, float* __restrict__ ctx)
{
    __shared__ float ks[HR][RANKD];
    __shared__ float vs[HR][RANKD];
    const int a = blockIdx.x, b = blockIdx.y;
    const int l = threadIdx.x;

    const size_t kvbase = ((size_t)b * AH + a) * HR * RANKD;
    for (int i = threadIdx.x; i < HR * RANKD; i += 128) {
        ((float*)ks)[i] = kf[kvbase + i];
        ((float*)vs)[i] = vf[kvbase + i];
    }
    __syncthreads();

    const float* Qb = Qp + ((size_t)b * SEQQ + a * 32) * DIM;

    float sc[RANKD];
#pragma unroll
    for (int r = 0; r < RANKD; r++) sc[r] = 0.f;

    for (int h = 0; h < HR; h++) {
        float qv = Qb[(h >> 3) * DIM + (h & 7) * LQ + l];
#pragma unroll
        for (int r = 0; r < RANKD; r++)
            sc[r] = fmaf(qv, ks[h][r], sc[r]);
    }

    float mx = -1e30f;
#pragma unroll
    for (int r = 0; r < RANKD; r++) { sc[r] *= 0.0625f; mx = fmaxf(mx, sc[r]); }
    float sum = 0.f;
#pragma unroll
    for (int r = 0; r < RANKD; r++) { sc[r] = expf(sc[r] - mx); sum += sc[r]; }
    float inv = 1.f / sum;
#pragma unroll
    for (int r = 0; r < RANKD; r++) sc[r] *= inv;

    float* crow = ctx + ((size_t)b * SEQQ + a * 32 + (l >> 2)) * DIM + (l & 3) * 256;
    for (int h0 = 0; h0 < HR; h0 += 4) {
        float o[4];
#pragma unroll
        for (int s = 0; s < 4; s++) {
            float v = 0.f;
#pragma unroll
            for (int r = 0; r < RANKD; r++)
                v = fmaf(sc[r], vs[h0 + s][r], v);
            o[s] = v;
        }
        *(float4*)&crow[h0] = make_float4(o[0], o[1], o[2], o[3]);
    }
}

// ============================================================================
// Residual + LayerNorm over dim=1024. One block (256 threads) per row.
// ============================================================================
__global__ __launch_bounds__(256)
void ln_residual(const float* __restrict__ Y, const float* __restrict__ Q,
                 const float* __restrict__ gamma, const float* __restrict__ beta,
                 float* __restrict__ out)
{
    const int row = blockIdx.x;
    const int tid = threadIdx.x;
    const float* y = Y + (size_t)row * DIM;
    const float* q = Q + (size_t)row * DIM;

    float x[4];
    float sum = 0.f, sq = 0.f;
#pragma unroll
    for (int i = 0; i < 4; i++) {
        int c = tid + i * 256;
        float v = y[c] + q[c];
        x[i] = v; sum += v; sq += v * v;
    }
#pragma unroll
    for (int o = 16; o; o >>= 1) {
        sum += __shfl_xor_sync(0xffffffffu, sum, o);
        sq  += __shfl_xor_sync(0xffffffffu, sq,  o);
    }
    __shared__ float rs[8], rq[8];
    __shared__ float smu, sinv;
    if ((tid & 31) == 0) { rs[tid >> 5] = sum; rq[tid >> 5] = sq; }
    __syncthreads();
    if (tid == 0) {
        float s = 0.f, s2 = 0.f;
        for (int i = 0; i < 8; i++) { s += rs[i]; s2 += rq[i]; }
        float mu  = s  * (1.0f / DIM);
        float var = s2 * (1.0f / DIM) - mu * mu;
        smu = mu;
        sinv = rsqrtf(var + 1e-5f);
    }
    __syncthreads();
    float mu = smu, inv = sinv;
    float* o = out + (size_t)row * DIM;
#pragma unroll
    for (int i = 0; i < 4; i++) {
        int c = tid + i * 256;
        o[c] = (x[i] - mu) * inv * gamma[c] + beta[c];
    }
}

// ============================================================================
// kernel_launch: 8 graph-capturable launches on the default stream.
// ============================================================================
extern "C" void kernel_launch(void* const* d_in, const int* in_sizes, int n_in,
                              void* d_out, int out_size)
{
    const float* Q   = (const float*)d_in[0];
    const float* K   = (const float*)d_in[1];
    const float* V   = (const float*)d_in[2];
    const float* WQ  = (const float*)d_in[3];
    const float* bQ  = (const float*)d_in[4];
    const float* WK  = (const float*)d_in[5];
    const float* bK  = (const float*)d_in[6];
    const float* WV  = (const float*)d_in[7];
    const float* bV  = (const float*)d_in[8];
    const float* fac = (const float*)d_in[9];
    const float* W1  = (const float*)d_in[10];
    const float* b1  = (const float*)d_in[11];
    const float* W2  = (const float*)d_in[12];
    const float* b2  = (const float*)d_in[13];
    const float* gam = (const float*)d_in[14];
    const float* bet = (const float*)d_in[15];
    float* out = (float*)d_out;

    float *Qp, *Kp, *Vp, *kf, *vf, *ctx, *h1, *y;
    cudaGetSymbolAddress((void**)&Qp,  g_Qp);
    cudaGetSymbolAddress((void**)&Kp,  g_Kp);
    cudaGetSymbolAddress((void**)&Vp,  g_Vp);
    cudaGetSymbolAddress((void**)&kf,  g_kf);
    cudaGetSymbolAddress((void**)&vf,  g_vf);
    cudaGetSymbolAddress((void**)&ctx, g_ctx);
    cudaGetSymbolAddress((void**)&h1,  g_h1);
    cudaGetSymbolAddress((void**)&y,   g_y);

    static bool attr_done = false;
    if (!attr_done) {
        cudaFuncSetAttribute(tgemm_bias<false>,
                             cudaFuncAttributeMaxDynamicSharedMemorySize, GEMM_SMEM);
        cudaFuncSetAttribute(tgemm_bias<true>,
                             cudaFuncAttributeMaxDynamicSharedMemorySize, GEMM_SMEM);
        attr_done = true;
    }

    const int MQ = BS_ * SEQQ;   // 32768
    const int MK = BS_ * KDIM;   // 16384

    // Projections (TF32 mma.sync, 64x64 warp tiles, cp.async double-buffered)
    tgemm_bias<false><<<dim3(DIM / 128, MQ / 128), 128, GEMM_SMEM>>>(Q, WQ, bQ, Qp, MQ, DIM, DIM);
    tgemm_bias<false><<<dim3(DIM / 128, MK / 128), 128, GEMM_SMEM>>>(K, WK, bK, Kp, MK, DIM, DIM);
    tgemm_bias<false><<<dim3(DIM / 128, MK / 128), 128, GEMM_SMEM>>>(V, WV, bV, Vp, MK, DIM, DIM);

    // Low-rank factor projection of K/V
    factor_kernel<<<dim3(AH, BS_), 256>>>(Kp, Vp, fac, kf, vf);

    // Fused attention
    attn_kernel<<<dim3(AH, BS_), 128>>>(Qp, kf, vf, ctx);

    // FFN
    tgemm_bias<true ><<<dim3(HID / 128, MQ / 128), 128, GEMM_SMEM>>>(ctx, W1, b1, h1, MQ, HID, DIM);
    tgemm_bias<false><<<dim3(DIM / 128, MQ / 128), 128, GEMM_SMEM>>>(h1,  W2, b2, y,  MQ, DIM, HID);

    // Residual + LayerNorm
    ln_residual<<<MQ, 256>>>(y, Q, gam, bet, out);
}